// round 2
// baseline (speedup 1.0000x reference)
#include <cuda_runtime.h>

#define NROWS 65536
#define DDIM 512
#define NUM_LABELS 512
#define NUM_DEMOG 4
#define NGROUP (NUM_LABELS * NUM_DEMOG)

// -------- scratch (device globals; no allocation allowed) --------
__device__ int    g_cnt[NGROUP];
__device__ int    g_off[NGROUP + 1];
__device__ int    g_cursor[NGROUP];
__device__ int    g_sorted[NROWS];
__device__ int    g_seg[NROWS];
__device__ double g_gm[NGROUP];
__device__ int    g_is64;
__device__ int    g_hist_done;
__device__ int    g_group_done;

// ================= k_init: zero counters + dtype detect =================
__global__ void k_init(const int* labels_raw) {
    int t = threadIdx.x;               // 1024 threads
    g_cnt[t]        = 0;
    g_cnt[t + 1024] = 0;
    if (t == 0) {
        // int64 labels in [0,512) => every odd int32 word (high word) is 0.
        int nz = 0;
        for (int i = 1; i < 64; i += 2) nz += (labels_raw[i] != 0);
        g_is64 = (nz == 0) ? 1 : 0;
        g_hist_done = 0;
        g_group_done = 0;
    }
}

__device__ __forceinline__ int load_idx_val(const void* p, int i, int is64) {
    if (is64) return (int)((const long long*)p)[i];
    return ((const int*)p)[i];
}

// ============ k_hist_scan: histogram; last CTA does the prefix scan ============
__global__ void __launch_bounds__(1024) k_hist_scan(const void* labels, const void* demog) {
    int i = blockIdx.x * 1024 + threadIdx.x;   // 64 blocks x 1024 = 65536 exactly
    int is64 = g_is64;
    int lab = load_idx_val(labels, i, is64);
    int dem = load_idx_val(demog, i, is64);
    int seg = dem * NUM_LABELS + lab;
    g_seg[i] = seg;
    atomicAdd(&g_cnt[seg], 1);

    // last-CTA-done ticket
    __shared__ int s_last;
    __syncthreads();
    if (threadIdx.x == 0) {
        __threadfence();
        s_last = (atomicAdd(&g_hist_done, 1) == gridDim.x - 1) ? 1 : 0;
    }
    __syncthreads();
    if (!s_last) return;
    __threadfence();   // acquire: all g_cnt atomics visible

    // ---- shuffle-based exclusive scan over 2048 counts (2 per thread) ----
    int t = threadIdx.x;
    int lane = t & 31, warp = t >> 5;
    int a = g_cnt[2 * t];
    int b = g_cnt[2 * t + 1];
    int pair = a + b;
    int v = pair;
    #pragma unroll
    for (int d = 1; d < 32; d <<= 1) {
        int u = __shfl_up_sync(0xffffffffu, v, d);
        if (lane >= d) v += u;
    }
    __shared__ int wsum[32];
    if (lane == 31) wsum[warp] = v;
    __syncthreads();
    if (warp == 0) {
        int w = wsum[lane];
        int x = w;
        #pragma unroll
        for (int d = 1; d < 32; d <<= 1) {
            int u = __shfl_up_sync(0xffffffffu, x, d);
            if (lane >= d) x += u;
        }
        wsum[lane] = x - w;   // exclusive warp prefix
    }
    __syncthreads();
    int incl = v + wsum[warp];
    int excl = incl - pair;
    g_off[2 * t]        = excl;
    g_off[2 * t + 1]    = excl + a;
    g_cursor[2 * t]     = excl;
    g_cursor[2 * t + 1] = excl + a;
    if (t == 1023) g_off[2048] = incl;
}

// ================= k_scatter: group-sorted row index list =================
__global__ void __launch_bounds__(1024) k_scatter() {
    int i = blockIdx.x * 1024 + threadIdx.x;
    int seg = g_seg[i];
    int pos = atomicAdd(&g_cursor[seg], 1);
    g_sorted[pos] = i;
}

// ===== k_group: one CTA per group; last CTA also computes the final loss =====
// grp_mean_dist = (sum||x||^2 - ||sum x||^2 / cnt) / cnt
__global__ void __launch_bounds__(128) k_group(const float4* __restrict__ feats,
                                               float* __restrict__ out) {
    int g = blockIdx.x;
    int t = threadIdx.x;   // thread t owns columns [4t, 4t+4)
    int start = g_off[g];
    int end   = g_off[g + 1];

    __shared__ int    sidx[128];
    __shared__ double red[128];
    __shared__ double red2[128];

    float4 acc = make_float4(0.f, 0.f, 0.f, 0.f);
    float ssqa0 = 0.f, ssqa1 = 0.f, ssqa2 = 0.f, ssqa3 = 0.f;

    for (int base = start; base < end; base += 128) {
        int n = min(128, end - base);
        __syncthreads();
        if (t < n) sidx[t] = g_sorted[base + t];
        __syncthreads();

        int r = 0;
        for (; r + 8 <= n; r += 8) {
            float4 v[8];
            #pragma unroll
            for (int j = 0; j < 8; ++j)
                v[j] = feats[(size_t)sidx[r + j] * 128 + t];
            #pragma unroll
            for (int j = 0; j < 8; ++j) {
                acc.x += v[j].x; acc.y += v[j].y; acc.z += v[j].z; acc.w += v[j].w;
            }
            #pragma unroll
            for (int j = 0; j < 8; ++j) {
                float s = v[j].x * v[j].x + v[j].y * v[j].y +
                          v[j].z * v[j].z + v[j].w * v[j].w;
                switch (j & 3) {
                    case 0: ssqa0 += s; break;
                    case 1: ssqa1 += s; break;
                    case 2: ssqa2 += s; break;
                    default: ssqa3 += s; break;
                }
            }
        }
        for (; r < n; ++r) {
            float4 v = feats[(size_t)sidx[r] * 128 + t];
            acc.x += v.x; acc.y += v.y; acc.z += v.z; acc.w += v.w;
            ssqa0 += v.x * v.x + v.y * v.y + v.z * v.z + v.w * v.w;
        }
    }

    double nrm = (double)acc.x * acc.x + (double)acc.y * acc.y +
                 (double)acc.z * acc.z + (double)acc.w * acc.w;
    double ssq = (double)ssqa0 + (double)ssqa1 + (double)ssqa2 + (double)ssqa3;

    __syncthreads();
    red[t]  = ssq;
    red2[t] = nrm;
    __syncthreads();
    #pragma unroll
    for (int s = 64; s > 0; s >>= 1) {
        if (t < s) { red[t] += red[t + s]; red2[t] += red2[t + s]; }
        __syncthreads();
    }
    if (t == 0) {
        int cnt = end - start;
        double denom = (cnt > 0) ? (double)cnt : 1.0;
        g_gm[g] = (red[0] - red2[0] / denom) / denom;
    }

    // ---- last-CTA-done: fused finalize ----
    __shared__ int s_last;
    if (t == 0) {
        __threadfence();
        s_last = (atomicAdd(&g_group_done, 1) == NGROUP - 1) ? 1 : 0;
    }
    __syncthreads();
    if (!s_last) return;
    __threadfence();   // acquire: all g_gm visible

    __shared__ double fsum[NUM_DEMOG][128];
    __shared__ int    fcnt[NUM_DEMOG][128];
    double lsum[NUM_DEMOG] = {0.0, 0.0, 0.0, 0.0};
    int    lcnt[NUM_DEMOG] = {0, 0, 0, 0};
    for (int gg = t; gg < NGROUP; gg += 128) {
        int c = g_off[gg + 1] - g_off[gg];
        if (c > 0) {
            int d = gg >> 9;   // / NUM_LABELS
            lsum[d] += g_gm[gg];
            lcnt[d] += 1;
        }
    }
    #pragma unroll
    for (int d = 0; d < NUM_DEMOG; ++d) { fsum[d][t] = lsum[d]; fcnt[d][t] = lcnt[d]; }
    __syncthreads();
    #pragma unroll
    for (int s = 64; s > 0; s >>= 1) {
        if (t < s) {
            #pragma unroll
            for (int d = 0; d < NUM_DEMOG; ++d) {
                fsum[d][t] += fsum[d][t + s];
                fcnt[d][t] += fcnt[d][t + s];
            }
        }
        __syncthreads();
    }
    if (t == 0) {
        double intra[NUM_DEMOG];
        double mu = 0.0;
        #pragma unroll
        for (int d = 0; d < NUM_DEMOG; ++d) {
            int np = fcnt[d][0] > 0 ? fcnt[d][0] : 1;
            intra[d] = fsum[d][0] / (double)np;
            mu += intra[d];
        }
        mu /= (double)NUM_DEMOG;
        double loss = 0.0;
        #pragma unroll
        for (int d = 0; d < NUM_DEMOG; ++d) loss += fabs(intra[d] - mu);
        loss /= (double)NUM_DEMOG;
        out[0] = (float)loss;
    }
}

extern "C" void kernel_launch(void* const* d_in, const int* in_sizes, int n_in,
                              void* d_out, int out_size) {
    const float* feats  = (const float*)d_in[0];
    const void*  labels = d_in[1];
    const void*  demog  = d_in[2];
    float* out = (float*)d_out;

    k_init<<<1, 1024>>>((const int*)labels);
    k_hist_scan<<<64, 1024>>>(labels, demog);
    k_scatter<<<64, 1024>>>();
    k_group<<<NGROUP, 128>>>((const float4*)feats, out);
}